// round 3
// baseline (speedup 1.0000x reference)
#include <cuda_runtime.h>
#include <math.h>

// ---------------- problem constants ----------------
#define TT    4096
#define DMODEL 2048
#define NH    16
#define DQK   192     // 128 nope + 64 rope
#define DNOPE 128
#define DROPE 64
#define DV    128
#define RANK  512
#define KVF   (RANK + DROPE)   // 576
#define QSTRIDE (NH * DQK)     // 3072
#define KVBSTRIDE (NH * (DNOPE + DV)) // 4096
#define OSTRIDE (NH * DV)      // 2048
#define SCALE 0.07216878364870323f   // 192^-0.5

// ---------------- scratch (no cudaMalloc allowed) ----------------
__device__ float g_q[TT * QSTRIDE];        // 4096 x 3072 (rope applied in place)
__device__ float g_kvfull[TT * KVF];       // 4096 x 576
__device__ float g_kvn[TT * RANK];         // 4096 x 512 (layernormed)
__device__ float g_kpe[TT * DROPE];        // 4096 x 64
__device__ float g_kvb[TT * KVBSTRIDE];    // 4096 x 4096 (k_nope | v per head)
__device__ float g_attn[TT * OSTRIDE];     // 4096 x 2048

// =================================================================
// Generic tiled GEMM: C[M,N] = A[M,K] @ B[N,K]^T   (both row-major,
// K contiguous). M%64==0, N%64==0, K%16==0 required (all shapes comply).
// 64x64 tile, BK=16, 256 threads, 4x4 per thread, smem stored k-major.
// =================================================================
__global__ void __launch_bounds__(256) gemm_nt(
    const float* __restrict__ A, const float* __restrict__ B,
    float* __restrict__ C, int M, int N, int K)
{
    __shared__ float As[16][64];
    __shared__ float Bs[16][64];
    const int tid = threadIdx.x;
    const int tx = tid & 15, ty = tid >> 4;
    const int bm = blockIdx.y * 64, bn = blockIdx.x * 64;
    const int lr = tid >> 2;            // 0..63
    const int lc = (tid & 3) << 2;      // 0,4,8,12

    float acc[4][4] = {};
    const float* Arow = A + (size_t)(bm + lr) * K + lc;
    const float* Brow = B + (size_t)(bn + lr) * K + lc;

    for (int k0 = 0; k0 < K; k0 += 16) {
        float4 av = *(const float4*)(Arow + k0);
        float4 bv = *(const float4*)(Brow + k0);
        As[lc + 0][lr] = av.x; As[lc + 1][lr] = av.y;
        As[lc + 2][lr] = av.z; As[lc + 3][lr] = av.w;
        Bs[lc + 0][lr] = bv.x; Bs[lc + 1][lr] = bv.y;
        Bs[lc + 2][lr] = bv.z; Bs[lc + 3][lr] = bv.w;
        __syncthreads();
#pragma unroll
        for (int kk = 0; kk < 16; kk++) {
            float4 a4 = *(const float4*)&As[kk][ty << 2];
            float4 b4 = *(const float4*)&Bs[kk][tx << 2];
            float ar[4] = {a4.x, a4.y, a4.z, a4.w};
            float br[4] = {b4.x, b4.y, b4.z, b4.w};
#pragma unroll
            for (int i = 0; i < 4; i++)
#pragma unroll
                for (int j = 0; j < 4; j++)
                    acc[i][j] += ar[i] * br[j];
        }
        __syncthreads();
    }
#pragma unroll
    for (int i = 0; i < 4; i++) {
        float4 o = make_float4(acc[i][0], acc[i][1], acc[i][2], acc[i][3]);
        *(float4*)&C[(size_t)(bm + ty * 4 + i) * N + bn + tx * 4] = o;
    }
}

// =================================================================
// RoPE on q_pe, in place.  idx over T*H*32 pairs.
// =================================================================
__global__ void rope_q_kernel(float* __restrict__ q)
{
    int idx = blockIdx.x * blockDim.x + threadIdx.x;   // < 4096*16*32
    int i = idx & 31;
    int h = (idx >> 5) & 15;
    int t = idx >> 9;
    double inv = pow(10000.0, -(double)(2 * i) / 64.0);
    double sd, cd;
    sincos((double)t * inv, &sd, &cd);
    float c = (float)cd, s = (float)sd;
    int base = t * QSTRIDE + h * DQK + DNOPE + 2 * i;
    float x1 = q[base], x2 = q[base + 1];
    q[base]     = x1 * c - x2 * s;
    q[base + 1] = x1 * s + x2 * c;
}

// =================================================================
// LayerNorm(kv) + RoPE(k_pe). One block per token row.
// =================================================================
__global__ void ln_ropek_kernel(
    const float* __restrict__ kvf, const float* __restrict__ gamma,
    const float* __restrict__ beta, float* __restrict__ kvn,
    float* __restrict__ kpe)
{
    int row = blockIdx.x, tid = threadIdx.x;
    __shared__ float s1[256], s2[256];
    float a = kvf[row * KVF + tid];
    float b = kvf[row * KVF + 256 + tid];
    s1[tid] = a + b;
    s2[tid] = a * a + b * b;
    __syncthreads();
    for (int s = 128; s > 0; s >>= 1) {
        if (tid < s) { s1[tid] += s1[tid + s]; s2[tid] += s2[tid + s]; }
        __syncthreads();
    }
    float mean = s1[0] * (1.f / 512.f);
    float var  = s2[0] * (1.f / 512.f) - mean * mean;
    float rstd = rsqrtf(var + 1e-5f);
    kvn[row * RANK + tid]       = (a - mean) * rstd * gamma[tid] + beta[tid];
    kvn[row * RANK + 256 + tid] = (b - mean) * rstd * gamma[256 + tid] + beta[256 + tid];
    if (tid < 32) {
        int i = tid;
        double inv = pow(10000.0, -(double)(2 * i) / 64.0);
        double sd, cd;
        sincos((double)row * inv, &sd, &cd);
        float x1 = kvf[row * KVF + RANK + 2 * i];
        float x2 = kvf[row * KVF + RANK + 2 * i + 1];
        kpe[row * DROPE + 2 * i]     = x1 * (float)cd - x2 * (float)sd;
        kpe[row * DROPE + 2 * i + 1] = x1 * (float)sd + x2 * (float)cd;
    }
}

// =================================================================
// Flash attention, causal, fp32.
// Block = (q-tile of 64 rows, head). 256 threads.
// Q/K smem k-major [192][64]; V [64][128]; S [64][65] padded.
// =================================================================
#define ATTN_SMEM_FLOATS (192*64 + 192*64 + 64*128 + 64*65 + 64 + 64 + 64 + 64*4)
#define ATTN_SMEM_BYTES  (ATTN_SMEM_FLOATS * 4)

__global__ void __launch_bounds__(256, 1) attn_kernel(
    const float* __restrict__ q, const float* __restrict__ kvb,
    const float* __restrict__ kpe, float* __restrict__ outp)
{
    extern __shared__ float sm[];
    float* Qs  = sm;                 // [192][64]
    float* Ks  = Qs + 192 * 64;      // [192][64]
    float* Vs  = Ks + 192 * 64;      // [64][128]
    float* Ss  = Vs + 64 * 128;      // [64][65]
    float* m_s = Ss + 64 * 65;       // [64]
    float* l_s = m_s + 64;           // [64]
    float* al  = l_s + 64;           // [64]
    float* ps  = al + 64;            // [64][4]

    const int tid = threadIdx.x;
    const int tx = tid & 15, ty = tid >> 4;
    const int h  = blockIdx.y;
    const int iq = (int)(gridDim.x - 1) - (int)blockIdx.x; // big tiles first
    const int q0 = iq * 64;
    const int lr = tid >> 2;      // 0..63
    const int seg = tid & 3;      // 0..3

    // ---- load Q tile (64 x 192), store k-major ----
    {
        const float* src = q + (size_t)(q0 + lr) * QSTRIDE + h * DQK + seg * 48;
#pragma unroll
        for (int u = 0; u < 12; u++) {
            float4 v = *(const float4*)(src + u * 4);
            int k = seg * 48 + u * 4;
            Qs[(k + 0) * 64 + lr] = v.x;
            Qs[(k + 1) * 64 + lr] = v.y;
            Qs[(k + 2) * 64 + lr] = v.z;
            Qs[(k + 3) * 64 + lr] = v.w;
        }
    }
    if (tid < 64) { m_s[tid] = -INFINITY; l_s[tid] = 0.f; }

    float oacc[4][8] = {};   // rows ty*4+i, cols tx*8+c

    for (int j = 0; j <= iq; j++) {
        __syncthreads();   // protects smem reuse (and Q/m/l init on iter 0)

        // ---- load K tile (k_nope | k_pe, k-major) and V tile ----
        {
            int t = j * 64 + lr;
            const float* kn = kvb + (size_t)t * KVBSTRIDE + h * 256;
            const float* kp = kpe + (size_t)t * DROPE;
#pragma unroll
            for (int u = 0; u < 12; u++) {
                int k = seg * 48 + u * 4;
                float4 v = (k < 128) ? *(const float4*)(kn + k)
                                     : *(const float4*)(kp + (k - 128));
                Ks[(k + 0) * 64 + lr] = v.x;
                Ks[(k + 1) * 64 + lr] = v.y;
                Ks[(k + 2) * 64 + lr] = v.z;
                Ks[(k + 3) * 64 + lr] = v.w;
            }
            const float* vp = kn + 128;
#pragma unroll
            for (int u = 0; u < 8; u++) {
                int c = seg * 32 + u * 4;
                *(float4*)&Vs[lr * 128 + c] = *(const float4*)(vp + c);
            }
        }
        __syncthreads();

        // ---- S = (Q K^T) * scale ----
        float s[4][4] = {};
#pragma unroll 4
        for (int k = 0; k < 192; k++) {
            float4 a4 = *(const float4*)&Qs[k * 64 + (ty << 2)];
            float4 b4 = *(const float4*)&Ks[k * 64 + (tx << 2)];
            float ar[4] = {a4.x, a4.y, a4.z, a4.w};
            float br[4] = {b4.x, b4.y, b4.z, b4.w};
#pragma unroll
            for (int i = 0; i < 4; i++)
#pragma unroll
                for (int jj = 0; jj < 4; jj++)
                    s[i][jj] += ar[i] * br[jj];
        }
#pragma unroll
        for (int i = 0; i < 4; i++)
#pragma unroll
            for (int jj = 0; jj < 4; jj++) {
                float v = s[i][jj] * SCALE;
                if (j == iq && (q0 + ty * 4 + i) < (j * 64 + tx * 4 + jj))
                    v = -INFINITY;
                Ss[(ty * 4 + i) * 65 + tx * 4 + jj] = v;
            }
        __syncthreads();

        // ---- online softmax: rowmax + rescale factor ----
        if (tid < 64) {
            float mx = -INFINITY;
#pragma unroll 8
            for (int c = 0; c < 64; c++) mx = fmaxf(mx, Ss[tid * 65 + c]);
            float mo = m_s[tid];
            float mn = fmaxf(mo, mx);
            al[tid]  = __expf(mo - mn);
            m_s[tid] = mn;
        }
        __syncthreads();

        // ---- exponentiate (all threads) + partial row sums ----
        {
            int r = tid >> 2;
            float mn = m_s[r];
            float sum = 0.f;
            int base = r * 65 + seg * 16;
#pragma unroll
            for (int c = 0; c < 16; c++) {
                float p = __expf(Ss[base + c] - mn);
                Ss[base + c] = p;
                sum += p;
            }
            ps[r * 4 + seg] = sum;
        }
        __syncthreads();
        if (tid < 64)
            l_s[tid] = l_s[tid] * al[tid]
                     + ps[tid * 4] + ps[tid * 4 + 1] + ps[tid * 4 + 2] + ps[tid * 4 + 3];
        __syncthreads();

        // ---- O = O*alpha + P @ V ----
#pragma unroll
        for (int i = 0; i < 4; i++) {
            float a = al[ty * 4 + i];
#pragma unroll
            for (int c = 0; c < 8; c++) oacc[i][c] *= a;
        }
#pragma unroll 2
        for (int kk = 0; kk < 64; kk++) {
            float4 v0 = *(const float4*)&Vs[kk * 128 + tx * 8];
            float4 v1 = *(const float4*)&Vs[kk * 128 + tx * 8 + 4];
#pragma unroll
            for (int i = 0; i < 4; i++) {
                float p = Ss[(ty * 4 + i) * 65 + kk];
                oacc[i][0] += p * v0.x; oacc[i][1] += p * v0.y;
                oacc[i][2] += p * v0.z; oacc[i][3] += p * v0.w;
                oacc[i][4] += p * v1.x; oacc[i][5] += p * v1.y;
                oacc[i][6] += p * v1.z; oacc[i][7] += p * v1.w;
            }
        }
    }
    __syncthreads();   // l_s complete

#pragma unroll
    for (int i = 0; i < 4; i++) {
        int r = ty * 4 + i;
        float inv = 1.f / l_s[r];
        float* dst = outp + (size_t)(q0 + r) * OSTRIDE + h * DV + tx * 8;
        float4 o0 = make_float4(oacc[i][0] * inv, oacc[i][1] * inv,
                                oacc[i][2] * inv, oacc[i][3] * inv);
        float4 o1 = make_float4(oacc[i][4] * inv, oacc[i][5] * inv,
                                oacc[i][6] * inv, oacc[i][7] * inv);
        *(float4*)(dst)     = o0;
        *(float4*)(dst + 4) = o1;
    }
}

// =================================================================
// launch
// =================================================================
extern "C" void kernel_launch(void* const* d_in, const int* in_sizes, int n_in,
                              void* d_out, int out_size)
{
    const float* x     = (const float*)d_in[0];
    const float* wq    = (const float*)d_in[1];
    const float* wkv_a = (const float*)d_in[2];
    const float* gamma = (const float*)d_in[3];
    const float* beta  = (const float*)d_in[4];
    const float* wkv_b = (const float*)d_in[5];
    const float* wo    = (const float*)d_in[6];
    float* out = (float*)d_out;

    float *gq, *gkvf, *gkvn, *gkpe, *gkvb, *gattn;
    cudaGetSymbolAddress((void**)&gq,    g_q);
    cudaGetSymbolAddress((void**)&gkvf,  g_kvfull);
    cudaGetSymbolAddress((void**)&gkvn,  g_kvn);
    cudaGetSymbolAddress((void**)&gkpe,  g_kpe);
    cudaGetSymbolAddress((void**)&gkvb,  g_kvb);
    cudaGetSymbolAddress((void**)&gattn, g_attn);

    // q = x @ wq^T        (4096 x 3072, K=2048)
    gemm_nt<<<dim3(3072 / 64, TT / 64), 256>>>(x, wq, gq, TT, 3072, DMODEL);
    // kv_full = x @ wkv_a^T (4096 x 576, K=2048)
    gemm_nt<<<dim3(KVF / 64, TT / 64), 256>>>(x, wkv_a, gkvf, TT, KVF, DMODEL);
    // rope(q_pe) in place
    rope_q_kernel<<<(TT * NH * 32) / 256, 256>>>(gq);
    // layernorm(kv) + rope(k_pe)
    ln_ropek_kernel<<<TT, 256>>>(gkvf, gamma, beta, gkvn, gkpe);
    // kvb = kvn @ wkv_b^T  (4096 x 4096, K=512)
    gemm_nt<<<dim3(KVBSTRIDE / 64, TT / 64), 256>>>(gkvn, wkv_b, gkvb, TT, KVBSTRIDE, RANK);
    // attention
    cudaFuncSetAttribute(attn_kernel, cudaFuncAttributeMaxDynamicSharedMemorySize,
                         ATTN_SMEM_BYTES);
    attn_kernel<<<dim3(TT / 64, NH), 256, ATTN_SMEM_BYTES>>>(gq, gkvb, gkpe, gattn);
    // out = attn @ wo^T    (4096 x 2048, K=2048)
    gemm_nt<<<dim3(DMODEL / 64, TT / 64), 256>>>(gattn, wo, out, TT, DMODEL, DMODEL);
}

// round 5
// speedup vs baseline: 2.5119x; 2.5119x over previous
#include <cuda_runtime.h>
#include <math.h>

// ---------------- problem constants ----------------
#define TT     4096
#define DMODEL 2048
#define NH     16
#define DQK    192     // 128 nope + 64 rope
#define DNOPE  128
#define DROPE  64
#define DV     128
#define RANK   512
#define KVF    (RANK + DROPE)          // 576
#define QSTRIDE (NH * DQK)             // 3072
#define KVBSTRIDE (NH * (DNOPE + DV))  // 4096
#define OSTRIDE (NH * DV)              // 2048
#define SCALE 0.07216878364870323f     // 192^-0.5

// ---------------- scratch (no cudaMalloc allowed) ----------------
__device__ float g_q[TT * QSTRIDE];
__device__ float g_kvfull[TT * KVF];
__device__ float g_kvn[TT * RANK];
__device__ float g_kpe[TT * DROPE];
__device__ float g_kvb[TT * KVBSTRIDE];
__device__ float g_attn[TT * OSTRIDE];
__device__ float g_cos[TT * 32];
__device__ float g_sin[TT * 32];

// ---------------- tf32 helpers ----------------
__device__ __forceinline__ unsigned f2tf(float x) {
    unsigned u;
    asm("cvt.rna.tf32.f32 %0, %1;" : "=r"(u) : "f"(x));
    return u;
}
__device__ __forceinline__ void mma_tf32(float c[4],
    unsigned a0, unsigned a1, unsigned a2, unsigned a3,
    unsigned b0, unsigned b1)
{
    asm volatile(
        "mma.sync.aligned.m16n8k8.row.col.f32.tf32.tf32.f32 "
        "{%0,%1,%2,%3},{%4,%5,%6,%7},{%8,%9},{%0,%1,%2,%3};"
        : "+f"(c[0]), "+f"(c[1]), "+f"(c[2]), "+f"(c[3])
        : "r"(a0), "r"(a1), "r"(a2), "r"(a3), "r"(b0), "r"(b1));
}

// =================================================================
// TF32 MMA GEMM: C[M,N] = A[M,K] @ B[N,K]^T, fp32 in/out.
// CTA tile 128x64, KC=32, 256 threads, warp tile 32x32.
// M%128==0, N%64==0, K%32==0 (all shapes comply).
// =================================================================
#define SA 36   // smem k-stride pad: g*36+tig mod 32 -> conflict-free frags

__global__ void __launch_bounds__(256) gemm_tf32(
    const float* __restrict__ A, const float* __restrict__ B,
    float* __restrict__ C, int M, int N, int K)
{
    __shared__ unsigned As[128 * SA];
    __shared__ unsigned Bs[64 * SA];
    const int tid = threadIdx.x;
    const int lane = tid & 31, w = tid >> 5;
    const int g = lane >> 2, tig = lane & 3;
    const int bm = blockIdx.y * 128, bn = blockIdx.x * 64;
    const int m0 = (w >> 1) * 32, n0 = (w & 1) * 32;

    float c[2][4][4] = {};

    const int arow = tid >> 1, acs = (tid & 1) * 16;
    const int brow = tid & 63, bcs = (tid >> 6) * 8;
    const float* Ap = A + (size_t)(bm + arow) * K + acs;
    const float* Bp = B + (size_t)(bn + brow) * K + bcs;

    for (int k0 = 0; k0 < K; k0 += 32) {
#pragma unroll
        for (int u = 0; u < 4; u++) {
            float4 v = *(const float4*)(Ap + k0 + u * 4);
            uint4 t = make_uint4(f2tf(v.x), f2tf(v.y), f2tf(v.z), f2tf(v.w));
            *(uint4*)&As[arow * SA + acs + u * 4] = t;
        }
#pragma unroll
        for (int u = 0; u < 2; u++) {
            float4 v = *(const float4*)(Bp + k0 + u * 4);
            uint4 t = make_uint4(f2tf(v.x), f2tf(v.y), f2tf(v.z), f2tf(v.w));
            *(uint4*)&Bs[brow * SA + bcs + u * 4] = t;
        }
        __syncthreads();
#pragma unroll
        for (int kk = 0; kk < 32; kk += 8) {
            unsigned a[2][4], b[4][2];
#pragma unroll
            for (int i = 0; i < 2; i++) {
                int r = m0 + i * 16;
                a[i][0] = As[(r + g) * SA + kk + tig];
                a[i][1] = As[(r + g + 8) * SA + kk + tig];
                a[i][2] = As[(r + g) * SA + kk + tig + 4];
                a[i][3] = As[(r + g + 8) * SA + kk + tig + 4];
            }
#pragma unroll
            for (int j = 0; j < 4; j++) {
                b[j][0] = Bs[(n0 + j * 8 + g) * SA + kk + tig];
                b[j][1] = Bs[(n0 + j * 8 + g) * SA + kk + tig + 4];
            }
#pragma unroll
            for (int i = 0; i < 2; i++)
#pragma unroll
                for (int j = 0; j < 4; j++)
                    mma_tf32(c[i][j], a[i][0], a[i][1], a[i][2], a[i][3],
                             b[j][0], b[j][1]);
        }
        __syncthreads();
    }
#pragma unroll
    for (int i = 0; i < 2; i++) {
        int r0 = bm + m0 + i * 16 + g;
#pragma unroll
        for (int j = 0; j < 4; j++) {
            int cc = bn + n0 + j * 8 + tig * 2;
            *(float2*)&C[(size_t)r0 * N + cc] = make_float2(c[i][j][0], c[i][j][1]);
            *(float2*)&C[(size_t)(r0 + 8) * N + cc] = make_float2(c[i][j][2], c[i][j][3]);
        }
    }
}

// =================================================================
// RoPE tables (double precision trig, computed once per launch)
// =================================================================
__global__ void rope_table_kernel()
{
    int idx = blockIdx.x * blockDim.x + threadIdx.x;   // < TT*32
    int i = idx & 31, t = idx >> 5;
    double inv = pow(10000.0, -(double)(2 * i) / 64.0);
    double sd, cd;
    sincos((double)t * inv, &sd, &cd);
    g_cos[idx] = (float)cd;
    g_sin[idx] = (float)sd;
}

// RoPE on q_pe, in place
__global__ void rope_q_kernel(float* __restrict__ q)
{
    int idx = blockIdx.x * blockDim.x + threadIdx.x;   // < TT*NH*32
    int i = idx & 31;
    int h = (idx >> 5) & 15;
    int t = idx >> 9;
    float c = g_cos[t * 32 + i], s = g_sin[t * 32 + i];
    int base = t * QSTRIDE + h * DQK + DNOPE + 2 * i;
    float x1 = q[base], x2 = q[base + 1];
    q[base]     = x1 * c - x2 * s;
    q[base + 1] = x1 * s + x2 * c;
}

// LayerNorm(kv) + RoPE(k_pe). One block per token row.
__global__ void ln_ropek_kernel(
    const float* __restrict__ kvf, const float* __restrict__ gamma,
    const float* __restrict__ beta, float* __restrict__ kvn,
    float* __restrict__ kpe)
{
    int row = blockIdx.x, tid = threadIdx.x;
    __shared__ float s1[256], s2[256];
    float a = kvf[row * KVF + tid];
    float b = kvf[row * KVF + 256 + tid];
    s1[tid] = a + b;
    s2[tid] = a * a + b * b;
    __syncthreads();
    for (int s = 128; s > 0; s >>= 1) {
        if (tid < s) { s1[tid] += s1[tid + s]; s2[tid] += s2[tid + s]; }
        __syncthreads();
    }
    float mean = s1[0] * (1.f / 512.f);
    float var  = s2[0] * (1.f / 512.f) - mean * mean;
    float rstd = rsqrtf(var + 1e-5f);
    kvn[row * RANK + tid]       = (a - mean) * rstd * gamma[tid] + beta[tid];
    kvn[row * RANK + 256 + tid] = (b - mean) * rstd * gamma[256 + tid] + beta[256 + tid];
    if (tid < 32) {
        int i = tid;
        float c = g_cos[row * 32 + i], s = g_sin[row * 32 + i];
        float x1 = kvf[row * KVF + RANK + 2 * i];
        float x2 = kvf[row * KVF + RANK + 2 * i + 1];
        kpe[row * DROPE + 2 * i]     = x1 * c - x2 * s;
        kpe[row * DROPE + 2 * i + 1] = x1 * s + x2 * c;
    }
}

// =================================================================
// Flash attention, causal, tf32 tensor-core compute.
// Block = (q-tile of 64 rows, head). 256 threads = 8 warps (4x2 grid).
// Smem (all padded for conflict-free mma fragment LDS):
//   Qs[64][196] tf32, Ks[64][196] tf32, Vs[64][136] tf32, Ss[64][68] f32.
// =================================================================
#define SQ 196
#define SV 136
#define SSP 68
#define ATTN_SMEM_BYTES ((64*SQ + 64*SQ + 64*SV + 64*SSP + 64*3 + 256) * 4)

__global__ void __launch_bounds__(256, 1) attn_kernel(
    const float* __restrict__ q, const float* __restrict__ kvb,
    const float* __restrict__ kpe, float* __restrict__ outp)
{
    extern __shared__ unsigned sm[];
    unsigned* Qs = sm;                    // [64][196] tf32 bits
    unsigned* Ks = Qs + 64 * SQ;          // [64][196]
    unsigned* Vs = Ks + 64 * SQ;          // [64][136]
    float* Ssm = (float*)(Vs + 64 * SV);  // [64][68]
    float* m_s = Ssm + 64 * SSP;          // [64]
    float* l_s = m_s + 64;                // [64]
    float* al  = l_s + 64;                // [64]
    float* ps  = al + 64;                 // [64][4]

    const int tid = threadIdx.x;
    const int lane = tid & 31, w = tid >> 5;
    const int g = lane >> 2, tig = lane & 3;
    const int m0 = (w >> 1) * 16;          // warp q-row base (0..48)
    const int wn = w & 1;
    const int n0 = wn * 32;                // QK col base
    const int n0p = wn * 64;               // PV col base
    const int h  = blockIdx.y;
    const int iq = (int)(gridDim.x - 1) - (int)blockIdx.x; // big tiles first
    const int q0 = iq * 64;
    const int lr = tid >> 2;               // 0..63
    const int seg = tid & 3;               // 0..3

    // ---- load Q tile (64 x 192) row-major, tf32 ----
    {
        const float* src = q + (size_t)(q0 + lr) * QSTRIDE + h * DQK + seg * 48;
#pragma unroll
        for (int u = 0; u < 12; u++) {
            float4 v = *(const float4*)(src + u * 4);
            uint4 t = make_uint4(f2tf(v.x), f2tf(v.y), f2tf(v.z), f2tf(v.w));
            *(uint4*)&Qs[lr * SQ + seg * 48 + u * 4] = t;
        }
    }
    if (tid < 64) { m_s[tid] = -INFINITY; l_s[tid] = 0.f; }

    float o[8][4] = {};   // PV accumulator fragments (8 n-subtiles)

    for (int jt = 0; jt <= iq; jt++) {
        __syncthreads();   // protects smem reuse (and Q/m/l init on iter 0)

        // ---- load K tile (k_nope | k_pe) + V tile, row-major, tf32 ----
        {
            int t = jt * 64 + lr;
            const float* kn = kvb + (size_t)t * KVBSTRIDE + h * 256;
            const float* kp = kpe + (size_t)t * DROPE;
#pragma unroll
            for (int u = 0; u < 12; u++) {
                int k = seg * 48 + u * 4;
                float4 v = (k < 128) ? *(const float4*)(kn + k)
                                     : *(const float4*)(kp + (k - 128));
                uint4 tt = make_uint4(f2tf(v.x), f2tf(v.y), f2tf(v.z), f2tf(v.w));
                *(uint4*)&Ks[lr * SQ + k] = tt;
            }
            const float* vp = kn + 128;
#pragma unroll
            for (int u = 0; u < 8; u++) {
                int cidx = seg * 32 + u * 4;
                float4 v = *(const float4*)(vp + cidx);
                uint4 tt = make_uint4(f2tf(v.x), f2tf(v.y), f2tf(v.z), f2tf(v.w));
                *(uint4*)&Vs[lr * SV + cidx] = tt;
            }
        }
        __syncthreads();

        // ---- S = Q K^T via tf32 mma (warp tile 16x32, K=192) ----
        float s[4][4] = {};
#pragma unroll
        for (int k0 = 0; k0 < 192; k0 += 8) {
            unsigned a0 = Qs[(m0 + g) * SQ + k0 + tig];
            unsigned a1 = Qs[(m0 + 8 + g) * SQ + k0 + tig];
            unsigned a2 = Qs[(m0 + g) * SQ + k0 + tig + 4];
            unsigned a3 = Qs[(m0 + 8 + g) * SQ + k0 + tig + 4];
#pragma unroll
            for (int j = 0; j < 4; j++) {
                unsigned b0 = Ks[(n0 + j * 8 + g) * SQ + k0 + tig];
                unsigned b1 = Ks[(n0 + j * 8 + g) * SQ + k0 + tig + 4];
                mma_tf32(s[j], a0, a1, a2, a3, b0, b1);
            }
        }
        // write S with scale + causal mask
#pragma unroll
        for (int j = 0; j < 4; j++) {
            int col = n0 + j * 8 + tig * 2;
            int gc0 = jt * 64 + col, gc1 = gc0 + 1;
            int gr0 = q0 + m0 + g, gr1 = gr0 + 8;
            float v0 = (gr0 >= gc0) ? s[j][0] * SCALE : -INFINITY;
            float v1 = (gr0 >= gc1) ? s[j][1] * SCALE : -INFINITY;
            float v2 = (gr1 >= gc0) ? s[j][2] * SCALE : -INFINITY;
            float v3 = (gr1 >= gc1) ? s[j][3] * SCALE : -INFINITY;
            *(float2*)&Ssm[(m0 + g) * SSP + col]     = make_float2(v0, v1);
            *(float2*)&Ssm[(m0 + 8 + g) * SSP + col] = make_float2(v2, v3);
        }
        __syncthreads();

        // ---- online softmax: rowmax + rescale factor ----
        if (tid < 64) {
            float mx = -INFINITY;
#pragma unroll 8
            for (int c = 0; c < 64; c++) mx = fmaxf(mx, Ssm[tid * SSP + c]);
            float mo = m_s[tid];
            float mn = fmaxf(mo, mx);
            al[tid]  = __expf(mo - mn);
            m_s[tid] = mn;
        }
        __syncthreads();

        // ---- exponentiate + partial row sums (all 256 threads) ----
        {
            int r = tid >> 2;
            float mn = m_s[r];
            float sum = 0.f;
            int base = r * SSP + seg * 16;
#pragma unroll
            for (int c = 0; c < 16; c++) {
                float p = __expf(Ssm[base + c] - mn);
                Ssm[base + c] = p;
                sum += p;
            }
            ps[r * 4 + seg] = sum;
        }
        __syncthreads();
        if (tid < 64)
            l_s[tid] = l_s[tid] * al[tid]
                     + ps[tid * 4] + ps[tid * 4 + 1] + ps[tid * 4 + 2] + ps[tid * 4 + 3];

        // ---- O = O*alpha + P @ V via tf32 mma (warp tile 16x64, K=64) ----
        {
            float av0 = al[m0 + g], av1 = al[m0 + 8 + g];
#pragma unroll
            for (int nt = 0; nt < 8; nt++) {
                o[nt][0] *= av0; o[nt][1] *= av0;
                o[nt][2] *= av1; o[nt][3] *= av1;
            }
        }
#pragma unroll
        for (int k0 = 0; k0 < 64; k0 += 8) {
            unsigned a0 = f2tf(Ssm[(m0 + g) * SSP + k0 + tig]);
            unsigned a1 = f2tf(Ssm[(m0 + 8 + g) * SSP + k0 + tig]);
            unsigned a2 = f2tf(Ssm[(m0 + g) * SSP + k0 + tig + 4]);
            unsigned a3 = f2tf(Ssm[(m0 + 8 + g) * SSP + k0 + tig + 4]);
#pragma unroll
            for (int nt = 0; nt < 8; nt++) {
                unsigned b0 = Vs[(k0 + tig) * SV + n0p + nt * 8 + g];
                unsigned b1 = Vs[(k0 + tig + 4) * SV + n0p + nt * 8 + g];
                mma_tf32(o[nt], a0, a1, a2, a3, b0, b1);
            }
        }
    }
    __syncthreads();   // l_s complete

    {
        float inv0 = 1.f / l_s[m0 + g];
        float inv1 = 1.f / l_s[m0 + 8 + g];
        float* d0 = outp + (size_t)(q0 + m0 + g) * OSTRIDE + h * DV + n0p;
        float* d1 = outp + (size_t)(q0 + m0 + 8 + g) * OSTRIDE + h * DV + n0p;
#pragma unroll
        for (int nt = 0; nt < 8; nt++) {
            int cc = nt * 8 + tig * 2;
            *(float2*)(d0 + cc) = make_float2(o[nt][0] * inv0, o[nt][1] * inv0);
            *(float2*)(d1 + cc) = make_float2(o[nt][2] * inv1, o[nt][3] * inv1);
        }
    }
}

// =================================================================
// launch
// =================================================================
extern "C" void kernel_launch(void* const* d_in, const int* in_sizes, int n_in,
                              void* d_out, int out_size)
{
    const float* x     = (const float*)d_in[0];
    const float* wq    = (const float*)d_in[1];
    const float* wkv_a = (const float*)d_in[2];
    const float* gamma = (const float*)d_in[3];
    const float* beta  = (const float*)d_in[4];
    const float* wkv_b = (const float*)d_in[5];
    const float* wo    = (const float*)d_in[6];
    float* out = (float*)d_out;

    float *gq, *gkvf, *gkvn, *gkpe, *gkvb, *gattn;
    cudaGetSymbolAddress((void**)&gq,    g_q);
    cudaGetSymbolAddress((void**)&gkvf,  g_kvfull);
    cudaGetSymbolAddress((void**)&gkvn,  g_kvn);
    cudaGetSymbolAddress((void**)&gkpe,  g_kpe);
    cudaGetSymbolAddress((void**)&gkvb,  g_kvb);
    cudaGetSymbolAddress((void**)&gattn, g_attn);

    // rope tables
    rope_table_kernel<<<(TT * 32) / 256, 256>>>();
    // q = x @ wq^T        (4096 x 3072, K=2048)
    gemm_tf32<<<dim3(3072 / 64, TT / 128), 256>>>(x, wq, gq, TT, 3072, DMODEL);
    // kv_full = x @ wkv_a^T (4096 x 576, K=2048)
    gemm_tf32<<<dim3(KVF / 64, TT / 128), 256>>>(x, wkv_a, gkvf, TT, KVF, DMODEL);
    // rope(q_pe) in place
    rope_q_kernel<<<(TT * NH * 32) / 256, 256>>>(gq);
    // layernorm(kv) + rope(k_pe)
    ln_ropek_kernel<<<TT, 256>>>(gkvf, gamma, beta, gkvn, gkpe);
    // kvb = kvn @ wkv_b^T  (4096 x 4096, K=512)
    gemm_tf32<<<dim3(KVBSTRIDE / 64, TT / 128), 256>>>(gkvn, wkv_b, gkvb, TT, KVBSTRIDE, RANK);
    // attention
    cudaFuncSetAttribute(attn_kernel, cudaFuncAttributeMaxDynamicSharedMemorySize,
                         ATTN_SMEM_BYTES);
    attn_kernel<<<dim3(TT / 64, NH), 256, ATTN_SMEM_BYTES>>>(gq, gkvb, gkpe, gattn);
    // out = attn @ wo^T    (4096 x 2048, K=2048)
    gemm_tf32<<<dim3(DMODEL / 64, TT / 128), 256>>>(gattn, wo, out, TT, DMODEL, DMODEL);
}

// round 6
// speedup vs baseline: 2.9486x; 1.1739x over previous
#include <cuda_runtime.h>
#include <math.h>

// ---------------- problem constants ----------------
#define TT     4096
#define DMODEL 2048
#define NH     16
#define DQK    192     // 128 nope + 64 rope
#define DNOPE  128
#define DROPE  64
#define DV     128
#define RANK   512
#define KVF    (RANK + DROPE)          // 576
#define QSTRIDE (NH * DQK)             // 3072
#define KVBSTRIDE (NH * (DNOPE + DV))  // 4096
#define OSTRIDE (NH * DV)              // 2048
#define SCALE 0.07216878364870323f     // 192^-0.5

// ---------------- scratch (no cudaMalloc allowed) ----------------
__device__ float g_q[TT * QSTRIDE];
__device__ float g_kvfull[TT * KVF];
__device__ float g_kvn[TT * RANK];
__device__ float g_kpe[TT * DROPE];
__device__ float g_kvb[TT * KVBSTRIDE];
__device__ float g_attn[TT * OSTRIDE];
__device__ float g_cos[TT * 32];
__device__ float g_sin[TT * 32];

// ---------------- tf32 helpers ----------------
__device__ __forceinline__ unsigned f2tf(float x) {
    unsigned u;
    asm("cvt.rna.tf32.f32 %0, %1;" : "=r"(u) : "f"(x));
    return u;
}
__device__ __forceinline__ void mma_tf32(float c[4],
    unsigned a0, unsigned a1, unsigned a2, unsigned a3,
    unsigned b0, unsigned b1)
{
    asm volatile(
        "mma.sync.aligned.m16n8k8.row.col.f32.tf32.tf32.f32 "
        "{%0,%1,%2,%3},{%4,%5,%6,%7},{%8,%9},{%0,%1,%2,%3};"
        : "+f"(c[0]), "+f"(c[1]), "+f"(c[2]), "+f"(c[3])
        : "r"(a0), "r"(a1), "r"(a2), "r"(a3), "r"(b0), "r"(b1));
}

// =================================================================
// TF32 MMA GEMM v2: C[M,N] = A[M,K] @ B[N,K]^T, fp32 in/out.
// CTA tile 128 x (NFRAG*16), KC=32, 256 threads, double-buffered smem
// with register prefetch (one global-load stage in flight).
// Warp grid 4(m) x 2(n); warp tile 32 x (NFRAG*8).
// ROPE: apply rope to q_pe columns in the epilogue (wq projection).
// =================================================================
#define SA 36   // smem k-stride: bank = 4g + tig -> conflict-free

template<int NFRAG, bool ROPE>
__global__ void __launch_bounds__(256) gemm_tf32(
    const float* __restrict__ A, const float* __restrict__ B,
    float* __restrict__ C, int M, int N, int K)
{
    constexpr int BN  = NFRAG * 16;       // 128 or 64
    constexpr int ASZ = 128 * SA;
    constexpr int BSZ = BN * SA;
    extern __shared__ unsigned smemg[];
    unsigned* As = smemg;                 // [2][ASZ]
    unsigned* Bs = smemg + 2 * ASZ;       // [2][BSZ]

    const int tid = threadIdx.x;
    const int lane = tid & 31, w = tid >> 5;
    const int g = lane >> 2, tig = lane & 3;
    const int bm = blockIdx.y * 128, bn = blockIdx.x * BN;
    const int m0 = (w >> 1) * 32;
    const int n0 = (w & 1) * (BN / 2);

    // global loaders
    const int arow = tid >> 1, acs = (tid & 1) * 16;
    constexpr int TPR = 256 / BN;         // threads per B row (2 or 4)
    constexpr int BW  = 32 / TPR;         // B elems per thread (16 or 8)
    constexpr int NB4 = BW / 4;           // B float4s per thread (4 or 2)
    const int brow = tid / TPR, bcs = (tid % TPR) * BW;

    const float* Ap = A + (size_t)(bm + arow) * K + acs;
    const float* Bp = B + (size_t)(bn + brow) * K + bcs;

    float4 ra[4], rb[NB4];
    float c[2][NFRAG][4] = {};

    // prologue: stage 0
#pragma unroll
    for (int u = 0; u < 4; u++) ra[u] = *(const float4*)(Ap + u * 4);
#pragma unroll
    for (int u = 0; u < NB4; u++) rb[u] = *(const float4*)(Bp + u * 4);
#pragma unroll
    for (int u = 0; u < 4; u++) {
        uint4 t = make_uint4(f2tf(ra[u].x), f2tf(ra[u].y), f2tf(ra[u].z), f2tf(ra[u].w));
        *(uint4*)&As[arow * SA + acs + u * 4] = t;
    }
#pragma unroll
    for (int u = 0; u < NB4; u++) {
        uint4 t = make_uint4(f2tf(rb[u].x), f2tf(rb[u].y), f2tf(rb[u].z), f2tf(rb[u].w));
        *(uint4*)&Bs[brow * SA + bcs + u * 4] = t;
    }
    __syncthreads();

    int cur = 0;
    for (int k0 = 0; k0 < K; k0 += 32) {
        const bool more = (k0 + 32) < K;
        if (more) {
#pragma unroll
            for (int u = 0; u < 4; u++) ra[u] = *(const float4*)(Ap + k0 + 32 + u * 4);
#pragma unroll
            for (int u = 0; u < NB4; u++) rb[u] = *(const float4*)(Bp + k0 + 32 + u * 4);
        }
        const unsigned* Ac = As + cur * ASZ;
        const unsigned* Bc = Bs + cur * BSZ;
#pragma unroll
        for (int kk = 0; kk < 32; kk += 8) {
            unsigned a[2][4];
#pragma unroll
            for (int i = 0; i < 2; i++) {
                int r = m0 + i * 16 + g;
                a[i][0] = Ac[r * SA + kk + tig];
                a[i][1] = Ac[(r + 8) * SA + kk + tig];
                a[i][2] = Ac[r * SA + kk + tig + 4];
                a[i][3] = Ac[(r + 8) * SA + kk + tig + 4];
            }
#pragma unroll
            for (int j = 0; j < NFRAG; j++) {
                unsigned b0 = Bc[(n0 + j * 8 + g) * SA + kk + tig];
                unsigned b1 = Bc[(n0 + j * 8 + g) * SA + kk + tig + 4];
#pragma unroll
                for (int i = 0; i < 2; i++)
                    mma_tf32(c[i][j], a[i][0], a[i][1], a[i][2], a[i][3], b0, b1);
            }
        }
        if (more) {
            int nx = cur ^ 1;
#pragma unroll
            for (int u = 0; u < 4; u++) {
                uint4 t = make_uint4(f2tf(ra[u].x), f2tf(ra[u].y), f2tf(ra[u].z), f2tf(ra[u].w));
                *(uint4*)&As[nx * ASZ + arow * SA + acs + u * 4] = t;
            }
#pragma unroll
            for (int u = 0; u < NB4; u++) {
                uint4 t = make_uint4(f2tf(rb[u].x), f2tf(rb[u].y), f2tf(rb[u].z), f2tf(rb[u].w));
                *(uint4*)&Bs[nx * BSZ + brow * SA + bcs + u * 4] = t;
            }
        }
        __syncthreads();
        cur ^= 1;
    }

    // epilogue (optionally fused RoPE on q_pe columns)
#pragma unroll
    for (int i = 0; i < 2; i++) {
        int r0 = bm + m0 + i * 16 + g;
#pragma unroll
        for (int j = 0; j < NFRAG; j++) {
            int cc = bn + n0 + j * 8 + tig * 2;
            float v00 = c[i][j][0], v01 = c[i][j][1];
            float v10 = c[i][j][2], v11 = c[i][j][3];
            if (ROPE) {
                int hc = cc % DQK;
                if (hc >= DNOPE) {
                    int pi = (hc - DNOPE) >> 1;
                    float c0 = g_cos[r0 * 32 + pi], s0 = g_sin[r0 * 32 + pi];
                    float t0 = v00 * c0 - v01 * s0;
                    v01 = v00 * s0 + v01 * c0; v00 = t0;
                    float c1 = g_cos[(r0 + 8) * 32 + pi], s1 = g_sin[(r0 + 8) * 32 + pi];
                    float t1 = v10 * c1 - v11 * s1;
                    v11 = v10 * s1 + v11 * c1; v10 = t1;
                }
            }
            *(float2*)&C[(size_t)r0 * N + cc] = make_float2(v00, v01);
            *(float2*)&C[(size_t)(r0 + 8) * N + cc] = make_float2(v10, v11);
        }
    }
}

// =================================================================
// RoPE tables (double precision trig, once per launch)
// =================================================================
__global__ void rope_table_kernel()
{
    int idx = blockIdx.x * blockDim.x + threadIdx.x;   // < TT*32
    int i = idx & 31, t = idx >> 5;
    double inv = pow(10000.0, -(double)(2 * i) / 64.0);
    double sd, cd;
    sincos((double)t * inv, &sd, &cd);
    g_cos[idx] = (float)cd;
    g_sin[idx] = (float)sd;
}

// LayerNorm(kv) + RoPE(k_pe). One block per token row, shfl reduction.
__global__ void ln_ropek_kernel(
    const float* __restrict__ kvf, const float* __restrict__ gamma,
    const float* __restrict__ beta, float* __restrict__ kvn,
    float* __restrict__ kpe)
{
    int row = blockIdx.x, tid = threadIdx.x;
    __shared__ float red[16];
    float a = kvf[row * KVF + tid];
    float b = kvf[row * KVF + 256 + tid];
    float s1 = a + b, s2 = a * a + b * b;
#pragma unroll
    for (int off = 16; off; off >>= 1) {
        s1 += __shfl_xor_sync(0xffffffffu, s1, off);
        s2 += __shfl_xor_sync(0xffffffffu, s2, off);
    }
    if ((tid & 31) == 0) { red[tid >> 5] = s1; red[8 + (tid >> 5)] = s2; }
    __syncthreads();
    float t1 = 0.f, t2 = 0.f;
#pragma unroll
    for (int i = 0; i < 8; i++) { t1 += red[i]; t2 += red[8 + i]; }
    float mean = t1 * (1.f / 512.f);
    float var  = t2 * (1.f / 512.f) - mean * mean;
    float rstd = rsqrtf(var + 1e-5f);
    kvn[row * RANK + tid]       = (a - mean) * rstd * gamma[tid] + beta[tid];
    kvn[row * RANK + 256 + tid] = (b - mean) * rstd * gamma[256 + tid] + beta[256 + tid];
    if (tid < 32) {
        int i = tid;
        float c = g_cos[row * 32 + i], s = g_sin[row * 32 + i];
        float x1 = kvf[row * KVF + RANK + 2 * i];
        float x2 = kvf[row * KVF + RANK + 2 * i + 1];
        kpe[row * DROPE + 2 * i]     = x1 * c - x2 * s;
        kpe[row * DROPE + 2 * i + 1] = x1 * s + x2 * c;
    }
}

// =================================================================
// Flash attention, causal, tf32 tensor-core compute.
// Block = (q-tile of 64 rows, head). 256 threads = 8 warps (4x2 grid).
// Softmax reductions via __shfl_xor over 4-lane row groups.
// =================================================================
#define SQ 196
#define SV 136
#define SSP 68
#define ATTN_SMEM_BYTES ((64*SQ + 64*SQ + 64*SV + 64*SSP + 192) * 4)

__global__ void __launch_bounds__(256, 1) attn_kernel(
    const float* __restrict__ q, const float* __restrict__ kvb,
    const float* __restrict__ kpe, float* __restrict__ outp)
{
    extern __shared__ unsigned sm[];
    unsigned* Qs = sm;                    // [64][196] tf32 bits
    unsigned* Ks = Qs + 64 * SQ;          // [64][196]
    unsigned* Vs = Ks + 64 * SQ;          // [64][136]
    float* Ssm = (float*)(Vs + 64 * SV);  // [64][68]
    float* m_s = Ssm + 64 * SSP;          // [64]
    float* l_s = m_s + 64;                // [64]
    float* al  = l_s + 64;                // [64]

    const int tid = threadIdx.x;
    const int lane = tid & 31, w = tid >> 5;
    const int g = lane >> 2, tig = lane & 3;
    const int m0 = (w >> 1) * 16;          // warp q-row base
    const int wn = w & 1;
    const int n0 = wn * 32;                // QK col base
    const int n0p = wn * 64;               // PV col base
    const int h  = blockIdx.y;
    const int iq = (int)(gridDim.x - 1) - (int)blockIdx.x; // big tiles first
    const int q0 = iq * 64;
    const int lr = tid >> 2;               // 0..63
    const int seg = tid & 3;               // 0..3

    // ---- load Q tile (64 x 192), row-major tf32 ----
    {
        const float* src = q + (size_t)(q0 + lr) * QSTRIDE + h * DQK + seg * 48;
#pragma unroll
        for (int u = 0; u < 12; u++) {
            float4 v = *(const float4*)(src + u * 4);
            uint4 t = make_uint4(f2tf(v.x), f2tf(v.y), f2tf(v.z), f2tf(v.w));
            *(uint4*)&Qs[lr * SQ + seg * 48 + u * 4] = t;
        }
    }
    if (tid < 64) { m_s[tid] = -INFINITY; l_s[tid] = 0.f; }

    float o[8][4] = {};

    for (int jt = 0; jt <= iq; jt++) {
        __syncthreads();   // smem reuse barrier (and Q/m/l init on iter 0)

        // ---- load K (k_nope | k_pe) + V tiles, tf32 ----
        {
            int t = jt * 64 + lr;
            const float* kn = kvb + (size_t)t * KVBSTRIDE + h * 256;
            const float* kp = kpe + (size_t)t * DROPE;
#pragma unroll
            for (int u = 0; u < 12; u++) {
                int k = seg * 48 + u * 4;
                float4 v = (k < 128) ? *(const float4*)(kn + k)
                                     : *(const float4*)(kp + (k - 128));
                uint4 tt = make_uint4(f2tf(v.x), f2tf(v.y), f2tf(v.z), f2tf(v.w));
                *(uint4*)&Ks[lr * SQ + k] = tt;
            }
            const float* vp = kn + 128;
#pragma unroll
            for (int u = 0; u < 8; u++) {
                int cidx = seg * 32 + u * 4;
                float4 v = *(const float4*)(vp + cidx);
                uint4 tt = make_uint4(f2tf(v.x), f2tf(v.y), f2tf(v.z), f2tf(v.w));
                *(uint4*)&Vs[lr * SV + cidx] = tt;
            }
        }
        __syncthreads();

        // ---- S = Q K^T (warp tile 16x32, K=192) ----
        float s[4][4] = {};
#pragma unroll
        for (int k0 = 0; k0 < 192; k0 += 8) {
            unsigned a0 = Qs[(m0 + g) * SQ + k0 + tig];
            unsigned a1 = Qs[(m0 + 8 + g) * SQ + k0 + tig];
            unsigned a2 = Qs[(m0 + g) * SQ + k0 + tig + 4];
            unsigned a3 = Qs[(m0 + 8 + g) * SQ + k0 + tig + 4];
#pragma unroll
            for (int j = 0; j < 4; j++) {
                unsigned b0 = Ks[(n0 + j * 8 + g) * SQ + k0 + tig];
                unsigned b1 = Ks[(n0 + j * 8 + g) * SQ + k0 + tig + 4];
                mma_tf32(s[j], a0, a1, a2, a3, b0, b1);
            }
        }
#pragma unroll
        for (int j = 0; j < 4; j++) {
            int col = n0 + j * 8 + tig * 2;
            int gc0 = jt * 64 + col, gc1 = gc0 + 1;
            int gr0 = q0 + m0 + g, gr1 = gr0 + 8;
            float v0 = (gr0 >= gc0) ? s[j][0] * SCALE : -INFINITY;
            float v1 = (gr0 >= gc1) ? s[j][1] * SCALE : -INFINITY;
            float v2 = (gr1 >= gc0) ? s[j][2] * SCALE : -INFINITY;
            float v3 = (gr1 >= gc1) ? s[j][3] * SCALE : -INFINITY;
            *(float2*)&Ssm[(m0 + g) * SSP + col]     = make_float2(v0, v1);
            *(float2*)&Ssm[(m0 + 8 + g) * SSP + col] = make_float2(v2, v3);
        }
        __syncthreads();

        // ---- online softmax: 4 lanes per row, shfl reductions ----
        {
            int r = lr;                       // tid>>2
            float* row = &Ssm[r * SSP + seg * 16];
            float mx = -INFINITY;
#pragma unroll
            for (int cI = 0; cI < 16; cI++) mx = fmaxf(mx, row[cI]);
            mx = fmaxf(mx, __shfl_xor_sync(0xffffffffu, mx, 1));
            mx = fmaxf(mx, __shfl_xor_sync(0xffffffffu, mx, 2));
            float mo = m_s[r];
            float mn = fmaxf(mo, mx);
            float alpha = __expf(mo - mn);
            float sum = 0.f;
#pragma unroll
            for (int cI = 0; cI < 16; cI++) {
                float p = __expf(row[cI] - mn);
                row[cI] = p;
                sum += p;
            }
            sum += __shfl_xor_sync(0xffffffffu, sum, 1);
            sum += __shfl_xor_sync(0xffffffffu, sum, 2);
            if (seg == 0) {
                m_s[r] = mn;
                al[r]  = alpha;
                l_s[r] = l_s[r] * alpha + sum;
            }
        }
        __syncthreads();

        // ---- O = O*alpha + P @ V (warp tile 16x64, K=64) ----
        {
            float av0 = al[m0 + g], av1 = al[m0 + 8 + g];
#pragma unroll
            for (int nt = 0; nt < 8; nt++) {
                o[nt][0] *= av0; o[nt][1] *= av0;
                o[nt][2] *= av1; o[nt][3] *= av1;
            }
        }
#pragma unroll
        for (int k0 = 0; k0 < 64; k0 += 8) {
            unsigned a0 = f2tf(Ssm[(m0 + g) * SSP + k0 + tig]);
            unsigned a1 = f2tf(Ssm[(m0 + 8 + g) * SSP + k0 + tig]);
            unsigned a2 = f2tf(Ssm[(m0 + g) * SSP + k0 + tig + 4]);
            unsigned a3 = f2tf(Ssm[(m0 + 8 + g) * SSP + k0 + tig + 4]);
#pragma unroll
            for (int nt = 0; nt < 8; nt++) {
                unsigned b0 = Vs[(k0 + tig) * SV + n0p + nt * 8 + g];
                unsigned b1 = Vs[(k0 + tig + 4) * SV + n0p + nt * 8 + g];
                mma_tf32(o[nt], a0, a1, a2, a3, b0, b1);
            }
        }
    }
    __syncthreads();   // l_s complete

    {
        float inv0 = 1.f / l_s[m0 + g];
        float inv1 = 1.f / l_s[m0 + 8 + g];
        float* d0 = outp + (size_t)(q0 + m0 + g) * OSTRIDE + h * DV + n0p;
        float* d1 = outp + (size_t)(q0 + m0 + 8 + g) * OSTRIDE + h * DV + n0p;
#pragma unroll
        for (int nt = 0; nt < 8; nt++) {
            int cc = nt * 8 + tig * 2;
            *(float2*)(d0 + cc) = make_float2(o[nt][0] * inv0, o[nt][1] * inv0);
            *(float2*)(d1 + cc) = make_float2(o[nt][2] * inv1, o[nt][3] * inv1);
        }
    }
}

// =================================================================
// launch
// =================================================================
#define GSM8 (2 * (128 * SA + 128 * SA) * 4)
#define GSM4 (2 * (128 * SA + 64 * SA) * 4)

extern "C" void kernel_launch(void* const* d_in, const int* in_sizes, int n_in,
                              void* d_out, int out_size)
{
    const float* x     = (const float*)d_in[0];
    const float* wq    = (const float*)d_in[1];
    const float* wkv_a = (const float*)d_in[2];
    const float* gamma = (const float*)d_in[3];
    const float* beta  = (const float*)d_in[4];
    const float* wkv_b = (const float*)d_in[5];
    const float* wo    = (const float*)d_in[6];
    float* out = (float*)d_out;

    float *gq, *gkvf, *gkvn, *gkpe, *gkvb, *gattn;
    cudaGetSymbolAddress((void**)&gq,    g_q);
    cudaGetSymbolAddress((void**)&gkvf,  g_kvfull);
    cudaGetSymbolAddress((void**)&gkvn,  g_kvn);
    cudaGetSymbolAddress((void**)&gkpe,  g_kpe);
    cudaGetSymbolAddress((void**)&gkvb,  g_kvb);
    cudaGetSymbolAddress((void**)&gattn, g_attn);

    cudaFuncSetAttribute(gemm_tf32<8, true>,
                         cudaFuncAttributeMaxDynamicSharedMemorySize, GSM8);
    cudaFuncSetAttribute(gemm_tf32<8, false>,
                         cudaFuncAttributeMaxDynamicSharedMemorySize, GSM8);
    cudaFuncSetAttribute(gemm_tf32<4, false>,
                         cudaFuncAttributeMaxDynamicSharedMemorySize, GSM4);
    cudaFuncSetAttribute(attn_kernel,
                         cudaFuncAttributeMaxDynamicSharedMemorySize, ATTN_SMEM_BYTES);

    // rope tables
    rope_table_kernel<<<(TT * 32) / 256, 256>>>();
    // q = x @ wq^T (+fused rope on q_pe)   (4096 x 3072, K=2048)
    gemm_tf32<8, true><<<dim3(3072 / 128, TT / 128), 256, GSM8>>>(
        x, wq, gq, TT, 3072, DMODEL);
    // kv_full = x @ wkv_a^T  (4096 x 576, K=2048)
    gemm_tf32<4, false><<<dim3(KVF / 64, TT / 128), 256, GSM4>>>(
        x, wkv_a, gkvf, TT, KVF, DMODEL);
    // layernorm(kv) + rope(k_pe)
    ln_ropek_kernel<<<TT, 256>>>(gkvf, gamma, beta, gkvn, gkpe);
    // kvb = kvn @ wkv_b^T  (4096 x 4096, K=512)
    gemm_tf32<8, false><<<dim3(KVBSTRIDE / 128, TT / 128), 256, GSM8>>>(
        gkvn, wkv_b, gkvb, TT, KVBSTRIDE, RANK);
    // attention
    attn_kernel<<<dim3(TT / 64, NH), 256, ATTN_SMEM_BYTES>>>(gq, gkvb, gkpe, gattn);
    // out = attn @ wo^T  (4096 x 2048, K=2048)
    gemm_tf32<8, false><<<dim3(DMODEL / 128, TT / 128), 256, GSM8>>>(
        gattn, wo, out, TT, DMODEL, DMODEL);
}